// round 5
// baseline (speedup 1.0000x reference)
#include <cuda_runtime.h>

// loss = sum_{i,j} (s_i - b_j)^2  with s = A @ x, A:[5000,20], b:[5000], x:[20]
//      = N*sum(s^2) - 2*sum(s)*sum(b) + N*sum(b^2)
//
// Single kernel node: 20 blocks compute partials; the last block to finish
// (tracked via atomic counter) reduces the partials and writes the scalar.
// Counter is reset by the last block -> safe for CUDA-graph replay.

#define N_ROWS 5000
#define N_FEAT 20
#define TPB    256
#define NBLK   ((N_ROWS + TPB - 1) / TPB)   // 20 blocks

// Per-block partials: [ss, ss2, bs, bs2]. Overwritten every launch.
__device__ double g_partial[NBLK][4];
__device__ unsigned int g_count = 0;

__inline__ __device__ double warp_sum(double v) {
    #pragma unroll
    for (int o = 16; o > 0; o >>= 1)
        v += __shfl_down_sync(0xffffffffu, v, o);
    return v;
}

__global__ void ls_fused_kernel(const float* __restrict__ A,
                                const float* __restrict__ b,
                                const float* __restrict__ x,
                                float* __restrict__ out) {
    __shared__ float xs[N_FEAT];
    if (threadIdx.x < N_FEAT) xs[threadIdx.x] = x[threadIdx.x];
    __syncthreads();

    const int i = blockIdx.x * TPB + threadIdx.x;

    double ss = 0.0, ss2 = 0.0, bs = 0.0, bs2 = 0.0;
    if (i < N_ROWS) {
        // Row i of A: 20 floats = 80 bytes, 16B-aligned -> 5 float4 loads.
        const float4* row = reinterpret_cast<const float4*>(A + i * N_FEAT);
        float acc = 0.0f;
        #pragma unroll
        for (int k = 0; k < 5; k++) {
            float4 v = row[k];
            acc += v.x * xs[4 * k + 0];
            acc += v.y * xs[4 * k + 1];
            acc += v.z * xs[4 * k + 2];
            acc += v.w * xs[4 * k + 3];
        }
        float bv = b[i];
        ss  = (double)acc;
        ss2 = (double)acc * (double)acc;
        bs  = (double)bv;
        bs2 = (double)bv * (double)bv;
    }

    // Block reduction: warp shuffle, then cross-warp via shared.
    ss  = warp_sum(ss);
    ss2 = warp_sum(ss2);
    bs  = warp_sum(bs);
    bs2 = warp_sum(bs2);

    __shared__ double sm[4][TPB / 32];
    const int lane = threadIdx.x & 31;
    const int wid  = threadIdx.x >> 5;
    if (lane == 0) {
        sm[0][wid] = ss;
        sm[1][wid] = ss2;
        sm[2][wid] = bs;
        sm[3][wid] = bs2;
    }
    __syncthreads();

    if (wid == 0) {
        const int nw = TPB / 32;
        double v0 = (lane < nw) ? sm[0][lane] : 0.0;
        double v1 = (lane < nw) ? sm[1][lane] : 0.0;
        double v2 = (lane < nw) ? sm[2][lane] : 0.0;
        double v3 = (lane < nw) ? sm[3][lane] : 0.0;
        v0 = warp_sum(v0);
        v1 = warp_sum(v1);
        v2 = warp_sum(v2);
        v3 = warp_sum(v3);
        if (lane == 0) {
            g_partial[blockIdx.x][0] = v0;
            g_partial[blockIdx.x][1] = v1;
            g_partial[blockIdx.x][2] = v2;
            g_partial[blockIdx.x][3] = v3;
        }
    }

    // ---- last-block-done finalize (single kernel node) ----
    __shared__ bool isLast;
    if (threadIdx.x == 0) {
        __threadfence();  // make partial slot visible before the count bump
        unsigned int old = atomicAdd(&g_count, 1u);
        isLast = (old == (unsigned int)(gridDim.x - 1));
        if (isLast) g_count = 0;  // reset for graph replay
    }
    __syncthreads();

    if (isLast && wid == 0) {
        double t0 = 0.0, t1 = 0.0, t2 = 0.0, t3 = 0.0;
        if (lane < NBLK) {
            t0 = g_partial[lane][0];
            t1 = g_partial[lane][1];
            t2 = g_partial[lane][2];
            t3 = g_partial[lane][3];
        }
        t0 = warp_sum(t0);
        t1 = warp_sum(t1);
        t2 = warp_sum(t2);
        t3 = warp_sum(t3);
        if (lane == 0) {
            const double N = (double)N_ROWS;
            out[0] = (float)(N * t1 - 2.0 * t0 * t2 + N * t3);
        }
    }
}

extern "C" void kernel_launch(void* const* d_in, const int* in_sizes, int n_in,
                              void* d_out, int out_size) {
    const float* A = (const float*)d_in[0];  // [5000, 20]
    const float* b = (const float*)d_in[1];  // [5000]
    const float* x = (const float*)d_in[2];  // [20]
    float* out = (float*)d_out;              // scalar

    ls_fused_kernel<<<NBLK, TPB>>>(A, b, x, out);
}